// round 8
// baseline (speedup 1.0000x reference)
#include <cuda_runtime.h>
#include <cuda_fp16.h>
#include <stdint.h>

#define B_TOK 8192
#define DIM   2048
#define NEXP  8

#define BM 128
#define BN 256
#define BK 64
#define NKC (DIM / BK)          // 32
#define NNT (DIM / BN)          // 8
#define MAXTILES 72
#define STAGES 4
#define NCWARP 16               // compute warps
#define GTHREADS (NCWARP * 32 + 32)   // +1 producer warp = 544

#define TILE_A 16384
#define TILE_B 32768
#define STAGE_SZ 49152
#define OFF_B 16384
#define OFF_MB (STAGES * STAGE_SZ)       // full barriers: 4 x 8B
#define OFF_CONS (OFF_MB + 32)           // consumed barriers: 4 x 8B
#define OFF_ROWS (OFF_CONS + 32)
#define SMEM_REQ (OFF_ROWS + 512 + 1024)

#define NTB 32

// -------- device scratch --------
__device__ int d_bh[NTB][NEXP];
__device__ int d_boff[NTB][NEXP];
__device__ int d_poff[NEXP + 1];
__device__ int d_is64 = 1;
__device__ int d_done = 0;
__device__ int d_perm[MAXTILES * 128];

__device__ __align__(128) char g_xa[(size_t)MAXTILES * NKC * TILE_A];
__device__ __align__(128) char g_wb[(size_t)NEXP * NNT * NKC * TILE_B];

// ======================= helpers =======================
__device__ __forceinline__ uint32_t smem_u32(const void* p) {
    uint32_t a;
    asm("{ .reg .u64 t; cvta.to.shared.u64 t, %1; cvt.u32.u64 %0, t; }" : "=r"(a) : "l"(p));
    return a;
}
__device__ __forceinline__ uint32_t sw128(uint32_t off) { return off ^ ((off >> 3) & 0x70); }

__device__ __forceinline__ void ldsm_x4(uint32_t* r, uint32_t addr) {
    asm volatile("ldmatrix.sync.aligned.m8n8.x4.shared.b16 {%0,%1,%2,%3}, [%4];"
                 : "=r"(r[0]), "=r"(r[1]), "=r"(r[2]), "=r"(r[3]) : "r"(addr));
}
__device__ __forceinline__ void mma16816(float* d, const uint32_t* a, uint32_t b0, uint32_t b1) {
    asm volatile(
        "mma.sync.aligned.m16n8k16.row.col.f32.f16.f16.f32 "
        "{%0,%1,%2,%3}, {%4,%5,%6,%7}, {%8,%9}, {%0,%1,%2,%3};"
        : "+f"(d[0]), "+f"(d[1]), "+f"(d[2]), "+f"(d[3])
        : "r"(a[0]), "r"(a[1]), "r"(a[2]), "r"(a[3]), "r"(b0), "r"(b1));
}
__device__ __forceinline__ void bulk_g2s(uint32_t dst, const void* src, uint32_t bytes, uint32_t mbar) {
    asm volatile(
        "{\n\t.reg .u64 g;\n\tcvta.to.global.u64 g, %1;\n\t"
        "cp.async.bulk.shared::cluster.global.mbarrier::complete_tx::bytes [%0], [g], %2, [%3];\n\t}"
        :: "r"(dst), "l"(src), "r"(bytes), "r"(mbar) : "memory");
}
#define MBARRIER_INIT(addr, cnt) \
    asm volatile("mbarrier.init.shared.b64 [%0], %1;" :: "r"((uint32_t)(addr)), "r"((uint32_t)(cnt)) : "memory")
#define MBARRIER_EXPECT_TX(addr, tx) \
    asm volatile("mbarrier.arrive.expect_tx.shared.b64 _, [%0], %1;" :: "r"((uint32_t)(addr)), "r"((uint32_t)(tx)) : "memory")
#define MBARRIER_ARRIVE(addr) \
    asm volatile("mbarrier.arrive.shared.b64 _, [%0];" :: "r"((uint32_t)(addr)) : "memory")
#define MBARRIER_WAIT_PARITY(addr, par) do { \
    uint32_t _m = (uint32_t)(addr); uint32_t _p = (uint32_t)(par); uint32_t _done; \
    asm volatile("{\n\t.reg .pred p;\n\t" \
        "mbarrier.try_wait.parity.acquire.cta.shared::cta.b64 p, [%1], %2;\n\t" \
        "selp.b32 %0, 1, 0, p;\n\t}" : "=r"(_done) : "r"(_m), "r"(_p) : "memory"); \
    if (!_done) { \
        asm volatile("{\n\t.reg .pred P1;\n\t" \
            "WL_%=:\n\tmbarrier.try_wait.parity.acquire.cta.shared::cta.b64 P1, [%0], %1, 0x989680;\n\t" \
            "@P1 bra.uni WD_%=;\n\tbra.uni WL_%=;\n\tWD_%=:\n\t}" \
            :: "r"(_m), "r"(_p) : "memory"); \
    } \
} while (0)

__device__ __forceinline__ int expert_of(const int* v, int i) { return d_is64 ? v[2 * i] : v[i]; }

// ======================= K1: convw + init + detect =======================
#define KP 72
__global__ void k1_convw_init(const float* __restrict__ W, const int* __restrict__ v32) {
    const int bid = blockIdx.x + NNT * (blockIdx.y + NKC * blockIdx.z);
    const int t = threadIdx.x;

    if (bid < 36) {
        int i = bid * 256 + t;
        if (i < MAXTILES * 128) d_perm[i] = -1;
        if (bid == 0 && t == 0) d_done = 0;
    }
    if (bid >= 64 && bid < 96) {
        int i = (bid - 64) * 256 + t;
        if ((i & 1) && v32[i] != 0) d_is64 = 0;
    }

    __shared__ __half ts[256 * KP];
    const int nt = blockIdx.x, kc = blockIdx.y, e = blockIdx.z;
    const float* Wb = W + ((size_t)e * DIM + kc * BK) * DIM + nt * BN;
#pragma unroll
    for (int i = 0; i < 16; i++) {
        int v = i * 256 + t;
        int k = v >> 6, c4 = v & 63;
        float4 w = *(const float4*)(Wb + (size_t)k * DIM + c4 * 4);
        int n = c4 * 4;
        ts[(n + 0) * KP + k] = __float2half_rn(w.x);
        ts[(n + 1) * KP + k] = __float2half_rn(w.y);
        ts[(n + 2) * KP + k] = __float2half_rn(w.z);
        ts[(n + 3) * KP + k] = __float2half_rn(w.w);
    }
    __syncthreads();
    char* dst = g_wb + ((size_t)((e * NNT + nt) * NKC + kc)) * TILE_B;
#pragma unroll
    for (int q = 0; q < 8; q++) {
        uint4 val = *(const uint4*)&ts[t * KP + q * 8];
        *(uint4*)(dst + sw128((uint32_t)(t * 128 + q * 16))) = val;
    }
}

// ======================= K2: per-block hist + global scan =======================
__global__ void k2_hist_scan(const int* __restrict__ v32) {
    __shared__ int h[NEXP];
    const int t = threadIdx.x;
    const int b = blockIdx.x;
    if (t < NEXP) h[t] = 0;
    __syncthreads();
    int e = expert_of(v32, b * 256 + t);
    if (e >= 0 && e < NEXP) atomicAdd(&h[e], 1);
    __syncthreads();
    if (t < NEXP) d_bh[b][t] = h[t];
    __threadfence();
    if (t == 0) {
        int r = atomicAdd(&d_done, 1);
        if (r == NTB - 1) {
            int tot[NEXP];
            for (int ee = 0; ee < NEXP; ee++) {
                int s = 0;
                for (int bb = 0; bb < NTB; bb++) s += d_bh[bb][ee];
                tot[ee] = s;
            }
            int pacc = 0;
            d_poff[0] = 0;
            for (int ee = 0; ee < NEXP; ee++) {
                int base = pacc;
                pacc += ((tot[ee] + 127) / 128) * 128;
                d_poff[ee + 1] = pacc;
                int run = base;
                for (int bb = 0; bb < NTB; bb++) { d_boff[bb][ee] = run; run += d_bh[bb][ee]; }
            }
            d_done = 0;
            __threadfence();
        }
    }
}

// ======================= K3: deterministic scatter + convx =======================
__global__ void k3_scatter_convx(const int* __restrict__ v32, const float* __restrict__ x) {
    __shared__ short se[256];
    __shared__ int spos[256];
    const int t = threadIdx.x;
    const int tb = blockIdx.x, y = blockIdx.y;

    int e = expert_of(v32, tb * 256 + t);
    se[t] = (short)e;
    __syncthreads();
    int rank = 0;
    for (int j = 0; j < 256; j++) {
        if (j >= t) break;
        if (se[j] == (short)e) rank++;
    }
    int pos = (e >= 0 && e < NEXP) ? d_boff[tb][e] + rank : -1;
    spos[t] = pos;
    if (y == 0 && pos >= 0) d_perm[pos] = tb * 256 + t;
    __syncthreads();

    const int f = t & 63;
    const int jb = t >> 6;
    for (int rep = 0; rep < 64; rep++) {
        int j = rep * 4 + jb;
        int pos_j = spos[j];
        if (pos_j < 0) continue;
        float4 w = *(const float4*)(x + (size_t)(tb * 256 + j) * DIM + y * 256 + f * 4);
        __half2 h0 = __floats2half2_rn(w.x, w.y);
        __half2 h1 = __floats2half2_rn(w.z, w.w);
        uint2 hv;
        hv.x = *(uint32_t*)&h0; hv.y = *(uint32_t*)&h1;
        int tile = pos_j >> 7, r = pos_j & 127;
        int kc = y * 4 + (f >> 4);
        int c = f & 15;
        *(uint2*)(g_xa + ((size_t)tile * NKC + kc) * TILE_A + sw128((uint32_t)(r * 128 + c * 8))) = hv;
    }
}

// ======================= K4: grouped GEMM (16 compute warps + 1 producer) =======================
__device__ __forceinline__ void issue_stage(uint32_t A0, uint32_t mb, int chunk, int stage,
                                            int mt, int e, int nt) {
    uint32_t bar = mb + stage * 8;
    MBARRIER_EXPECT_TX(bar, (uint32_t)STAGE_SZ);
    const char* asrc = g_xa + ((size_t)(mt * NKC + chunk)) * TILE_A;
    const char* bsrc = g_wb + ((size_t)((e * NNT + nt) * NKC + chunk)) * TILE_B;
    uint32_t sb = A0 + stage * STAGE_SZ;
    bulk_g2s(sb, asrc, TILE_A, bar);
    bulk_g2s(sb + OFF_B, bsrc, TILE_B, bar);
}

__global__ void __launch_bounds__(GTHREADS, 1)
k_gemm(const float* __restrict__ bias, float* __restrict__ out)
{
    const int m0p = blockIdx.y * BM;
    if (m0p >= d_poff[NEXP]) return;
    int e = 0;
#pragma unroll
    for (int i = 0; i < NEXP; i++) if (m0p >= d_poff[i + 1]) e = i + 1;

    const int mt = blockIdx.y;
    const int nt = blockIdx.x;
    const int n0 = nt * BN;

    extern __shared__ char smraw[];
    const uint32_t A0 = (smem_u32(smraw) + 1023u) & ~1023u;
    const uint32_t mb = A0 + OFF_MB;      // full (tx) barriers
    const uint32_t cb = A0 + OFF_CONS;    // consumed barriers

    const int tid = threadIdx.x;
    const int wid = tid >> 5;
    const int lane = tid & 31;

    int* rows = (int*)(smraw + ((A0 + OFF_ROWS) - smem_u32(smraw)));
    if (tid < BM) rows[tid] = d_perm[m0p + tid];
    if (tid == 0) {
#pragma unroll
        for (int s = 0; s < STAGES; s++) {
            MBARRIER_INIT(mb + s * 8, 1);
            MBARRIER_INIT(cb + s * 8, NCWARP);
        }
    }
    __syncthreads();   // only block-wide sync: init + rows visible

    if (wid == NCWARP) {
        // ---------------- producer warp ----------------
        if (lane == 0) {
#pragma unroll
            for (int s = 0; s < STAGES; s++) issue_stage(A0, mb, s, s, mt, e, nt);
            for (int r = STAGES; r < NKC; r++) {
                const int s = r & (STAGES - 1);
                MBARRIER_WAIT_PARITY(cb + s * 8, ((r >> 2) - 1) & 1);
                issue_stage(A0, mb, r, s, mt, e, nt);
            }
        }
        return;
    }

    // ---------------- compute warps ----------------
    const int warp_m = wid >> 3;     // 0..1  -> 64 rows
    const int warp_n = wid & 7;      // 0..7  -> 32 cols

    float acc[4][4][4];
#pragma unroll
    for (int i = 0; i < 4; i++)
#pragma unroll
        for (int j = 0; j < 4; j++)
#pragma unroll
            for (int q = 0; q < 4; q++) acc[i][j][q] = 0.0f;

    const int lrow = lane & 15;
    const int lc16 = (lane >> 4) << 4;

    uint32_t a0off[4], b0off[2];
#pragma unroll
    for (int i = 0; i < 4; i++)
        a0off[i] = sw128((uint32_t)((warp_m * 64 + i * 16 + lrow) * 128 + lc16));
#pragma unroll
    for (int g = 0; g < 2; g++)
        b0off[g] = sw128((uint32_t)((warp_n * 32 + g * 16 + lrow) * 128 + lc16));

    for (int c = 0; c < NKC; c++) {
        const int s = c & (STAGES - 1);
        MBARRIER_WAIT_PARITY(mb + s * 8, (c >> 2) & 1);

        const uint32_t aA = A0 + s * STAGE_SZ;
        const uint32_t aB = aA + OFF_B;
#pragma unroll
        for (int ks = 0; ks < 4; ks++) {
            const uint32_t kx = (uint32_t)(ks << 5);
            uint32_t af[4][4];
#pragma unroll
            for (int i = 0; i < 4; i++) ldsm_x4(af[i], aA + (a0off[i] ^ kx));
            uint32_t bf[2][4];
#pragma unroll
            for (int g = 0; g < 2; g++) ldsm_x4(bf[g], aB + (b0off[g] ^ kx));
#pragma unroll
            for (int i = 0; i < 4; i++)
#pragma unroll
                for (int j = 0; j < 4; j++)
                    mma16816(acc[i][j], af[i], bf[j >> 1][j & 1], bf[j >> 1][(j & 1) + 2]);
        }
        if (lane == 0) MBARRIER_ARRIVE(cb + s * 8);
    }

    // epilogue: add bias, scatter rows (per-warp independent)
    const float* be = bias + (size_t)e * DIM;
#pragma unroll
    for (int i = 0; i < 4; i++) {
#pragma unroll
        for (int half = 0; half < 2; half++) {
            int mloc = warp_m * 64 + i * 16 + (lane >> 2) + half * 8;
            int grow = rows[mloc];
            if (grow < 0) continue;
            float* orow = out + (size_t)grow * DIM;
#pragma unroll
            for (int j = 0; j < 4; j++) {
                int col = n0 + warp_n * 32 + j * 8 + (lane & 3) * 2;
                float2 bb = *(const float2*)(be + col);
                float2 o;
                o.x = acc[i][j][half * 2 + 0] + bb.x;
                o.y = acc[i][j][half * 2 + 1] + bb.y;
                *(float2*)(orow + col) = o;
            }
        }
    }
}

// ======================= host =======================
extern "C" void kernel_launch(void* const* d_in, const int* in_sizes, int n_in,
                              void* d_out, int out_size)
{
    const float* x = nullptr;
    const float* W = nullptr;
    const float* b = nullptr;
    const void* idx = nullptr;
    for (int i = 0; i < n_in; i++) {
        long long sz = in_sizes[i];
        if      (sz == (long long)B_TOK * DIM)      x = (const float*)d_in[i];
        else if (sz == (long long)NEXP * DIM * DIM) W = (const float*)d_in[i];
        else if (sz == (long long)NEXP * DIM)       b = (const float*)d_in[i];
        else if (sz == (long long)B_TOK)            idx = d_in[i];
    }
    float* out = (float*)d_out;
    const int* v32 = (const int*)idx;

    cudaFuncSetAttribute(k_gemm, cudaFuncAttributeMaxDynamicSharedMemorySize, SMEM_REQ);

    dim3 wgrid(NNT, NKC, NEXP);
    k1_convw_init<<<wgrid, 256>>>(W, v32);           // launch 1
    k2_hist_scan<<<NTB, 256>>>(v32);                 // launch 2
    k3_scatter_convx<<<dim3(NTB, 8), 256>>>(v32, x); // launch 3
    dim3 ggrid(NNT, MAXTILES);
    k_gemm<<<ggrid, GTHREADS, SMEM_REQ>>>(b, out);   // launch 4 (ncu target)
}

// round 9
// speedup vs baseline: 1.3308x; 1.3308x over previous
#include <cuda_runtime.h>
#include <cuda_fp16.h>
#include <stdint.h>

#define B_TOK 8192
#define DIM   2048
#define NEXP  8

#define BM 128
#define BN 256
#define BK 128
#define NKC (DIM / BK)          // 16
#define NNT (DIM / BN)          // 8
#define MAXTILES 72
#define STAGES 2
#define GTHREADS 512            // 16 compute warps

#define TILE_A 32768            // 128m x 128k fp16, 2 k-subtiles of 16KB, SW128
#define TILE_B 65536            // 128k x 256n fp16, 4 n-subtiles of 16KB, SW128
#define STAGE_SZ (TILE_A + TILE_B)      // 98304
#define OFF_B TILE_A
#define OFF_MB (STAGES * STAGE_SZ)      // 196608
#define OFF_ROWS (OFF_MB + 64)
#define SMEM_REQ (OFF_ROWS + 512 + 1024)

#define NTB 32

// -------- device scratch --------
__device__ int d_bh[NTB][NEXP];
__device__ int d_boff[NTB][NEXP];
__device__ int d_poff[NEXP + 1];
__device__ int d_is64 = 1;
__device__ int d_done = 0;
__device__ int d_perm[MAXTILES * 128];

__device__ __align__(128) char g_xa[(size_t)MAXTILES * NKC * TILE_A];
__device__ __align__(128) char g_wb[(size_t)NEXP * NNT * NKC * TILE_B];

// ======================= helpers =======================
__device__ __forceinline__ uint32_t smem_u32(const void* p) {
    uint32_t a;
    asm("{ .reg .u64 t; cvta.to.shared.u64 t, %1; cvt.u32.u64 %0, t; }" : "=r"(a) : "l"(p));
    return a;
}
__device__ __forceinline__ uint32_t sw128(uint32_t off) { return off ^ ((off >> 3) & 0x70); }

__device__ __forceinline__ void ldsm_x4(uint32_t* r, uint32_t addr) {
    asm volatile("ldmatrix.sync.aligned.m8n8.x4.shared.b16 {%0,%1,%2,%3}, [%4];"
                 : "=r"(r[0]), "=r"(r[1]), "=r"(r[2]), "=r"(r[3]) : "r"(addr));
}
__device__ __forceinline__ void ldsm_x4_t(uint32_t* r, uint32_t addr) {
    asm volatile("ldmatrix.sync.aligned.m8n8.x4.trans.shared.b16 {%0,%1,%2,%3}, [%4];"
                 : "=r"(r[0]), "=r"(r[1]), "=r"(r[2]), "=r"(r[3]) : "r"(addr));
}
__device__ __forceinline__ void mma16816(float* d, const uint32_t* a, uint32_t b0, uint32_t b1) {
    asm volatile(
        "mma.sync.aligned.m16n8k16.row.col.f32.f16.f16.f32 "
        "{%0,%1,%2,%3}, {%4,%5,%6,%7}, {%8,%9}, {%0,%1,%2,%3};"
        : "+f"(d[0]), "+f"(d[1]), "+f"(d[2]), "+f"(d[3])
        : "r"(a[0]), "r"(a[1]), "r"(a[2]), "r"(a[3]), "r"(b0), "r"(b1));
}
__device__ __forceinline__ void bulk_g2s(uint32_t dst, const void* src, uint32_t bytes, uint32_t mbar) {
    asm volatile(
        "{\n\t.reg .u64 g;\n\tcvta.to.global.u64 g, %1;\n\t"
        "cp.async.bulk.shared::cluster.global.mbarrier::complete_tx::bytes [%0], [g], %2, [%3];\n\t}"
        :: "r"(dst), "l"(src), "r"(bytes), "r"(mbar) : "memory");
}
#define MBARRIER_INIT(addr, cnt) \
    asm volatile("mbarrier.init.shared.b64 [%0], %1;" :: "r"((uint32_t)(addr)), "r"((uint32_t)(cnt)) : "memory")
#define MBARRIER_EXPECT_TX(addr, tx) \
    asm volatile("mbarrier.arrive.expect_tx.shared.b64 _, [%0], %1;" :: "r"((uint32_t)(addr)), "r"((uint32_t)(tx)) : "memory")
#define MBARRIER_WAIT_PARITY(addr, par) do { \
    uint32_t _m = (uint32_t)(addr); uint32_t _p = (uint32_t)(par); uint32_t _done; \
    asm volatile("{\n\t.reg .pred p;\n\t" \
        "mbarrier.try_wait.parity.acquire.cta.shared::cta.b64 p, [%1], %2;\n\t" \
        "selp.b32 %0, 1, 0, p;\n\t}" : "=r"(_done) : "r"(_m), "r"(_p) : "memory"); \
    if (!_done) { \
        asm volatile("{\n\t.reg .pred P1;\n\t" \
            "WL_%=:\n\tmbarrier.try_wait.parity.acquire.cta.shared::cta.b64 P1, [%0], %1, 0x989680;\n\t" \
            "@P1 bra.uni WD_%=;\n\tbra.uni WL_%=;\n\tWD_%=:\n\t}" \
            :: "r"(_m), "r"(_p) : "memory"); \
    } \
} while (0)

__device__ __forceinline__ int expert_of(const int* v, int i) { return d_is64 ? v[2 * i] : v[i]; }

// ======================= K1: convw (K-major, no transpose) + init + detect =======================
// B tile (e,nt,kc): [k 0..127][n 0..255] fp16 as 4 n-subtiles of (128k x 64n),
// within subtile: offset = sw128(k*128 + (n&63)*2). Fully coalesced, no smem.
__global__ void k1_convw_init(const float* __restrict__ W, const int* __restrict__ v32) {
    const int bid = blockIdx.x + NNT * (blockIdx.y + NKC * blockIdx.z);  // 0..1023
    const int t = threadIdx.x;

    if (bid < 36) {
        int i = bid * 256 + t;
        if (i < MAXTILES * 128) d_perm[i] = -1;
        if (bid == 0 && t == 0) d_done = 0;
    }
    if (bid >= 64 && bid < 96) {
        int i = (bid - 64) * 256 + t;
        if ((i & 1) && v32[i] != 0) d_is64 = 0;
    }

    const int nt = blockIdx.x, kc = blockIdx.y, e = blockIdx.z;
    const float* Wb = W + ((size_t)e * DIM + kc * BK) * DIM + nt * BN;
    char* dst = g_wb + ((size_t)((e * NNT + nt) * NKC + kc)) * TILE_B;

#pragma unroll
    for (int i = 0; i < 16; i++) {
        int g = i * 256 + t;               // 0..4095 16B-granules
        int k = g >> 5;                    // 0..127
        int c = g & 31;                    // 16B col (n = c*8)
        const float4* s4 = (const float4*)(Wb + (size_t)k * DIM + c * 8);
        float4 w0 = s4[0];
        float4 w1 = s4[1];
        __half2 h0 = __floats2half2_rn(w0.x, w0.y);
        __half2 h1 = __floats2half2_rn(w0.z, w0.w);
        __half2 h2 = __floats2half2_rn(w1.x, w1.y);
        __half2 h3 = __floats2half2_rn(w1.z, w1.w);
        uint4 val;
        val.x = *(uint32_t*)&h0; val.y = *(uint32_t*)&h1;
        val.z = *(uint32_t*)&h2; val.w = *(uint32_t*)&h3;
        *(uint4*)(dst + ((c >> 3) << 14) + sw128((uint32_t)(k * 128 + (c & 7) * 16))) = val;
    }
}

// ======================= K2: per-block hist + global scan =======================
__global__ void k2_hist_scan(const int* __restrict__ v32) {
    __shared__ int h[NEXP];
    const int t = threadIdx.x;
    const int b = blockIdx.x;
    if (t < NEXP) h[t] = 0;
    __syncthreads();
    int e = expert_of(v32, b * 256 + t);
    if (e >= 0 && e < NEXP) atomicAdd(&h[e], 1);
    __syncthreads();
    if (t < NEXP) d_bh[b][t] = h[t];
    __threadfence();
    if (t == 0) {
        int r = atomicAdd(&d_done, 1);
        if (r == NTB - 1) {
            int tot[NEXP];
            for (int ee = 0; ee < NEXP; ee++) {
                int s = 0;
                for (int bb = 0; bb < NTB; bb++) s += d_bh[bb][ee];
                tot[ee] = s;
            }
            int pacc = 0;
            d_poff[0] = 0;
            for (int ee = 0; ee < NEXP; ee++) {
                int base = pacc;
                pacc += ((tot[ee] + 127) / 128) * 128;
                d_poff[ee + 1] = pacc;
                int run = base;
                for (int bb = 0; bb < NTB; bb++) { d_boff[bb][ee] = run; run += d_bh[bb][ee]; }
            }
            d_done = 0;
            __threadfence();
        }
    }
}

// ======================= K3: deterministic scatter + convx =======================
// A tile (mt,kc): [m 0..127][k 0..127] fp16 as 2 k-subtiles of (128m x 64k),
// within subtile: offset = sw128(m*128 + (k&63)*2).
__global__ void k3_scatter_convx(const int* __restrict__ v32, const float* __restrict__ x) {
    __shared__ short se[256];
    __shared__ int spos[256];
    const int t = threadIdx.x;
    const int tb = blockIdx.x, y = blockIdx.y;

    int e = expert_of(v32, tb * 256 + t);
    se[t] = (short)e;
    __syncthreads();
    int rank = 0;
    for (int j = 0; j < 256; j++) {
        if (j >= t) break;
        if (se[j] == (short)e) rank++;
    }
    int pos = (e >= 0 && e < NEXP) ? d_boff[tb][e] + rank : -1;
    spos[t] = pos;
    if (y == 0 && pos >= 0) d_perm[pos] = tb * 256 + t;
    __syncthreads();

    const int f = t & 63;                     // float4 index within 256-col slice
    const int jb = t >> 6;
    for (int rep = 0; rep < 64; rep++) {
        int j = rep * 4 + jb;
        int pos_j = spos[j];
        if (pos_j < 0) continue;
        float4 w = *(const float4*)(x + (size_t)(tb * 256 + j) * DIM + y * 256 + f * 4);
        __half2 h0 = __floats2half2_rn(w.x, w.y);
        __half2 h1 = __floats2half2_rn(w.z, w.w);
        uint2 hv;
        hv.x = *(uint32_t*)&h0; hv.y = *(uint32_t*)&h1;
        int tile = pos_j >> 7, r = pos_j & 127;
        int kc2  = y * 2 + (f >> 5);          // 128-k chunk
        int ksub = (f >> 4) & 1;              // k-subtile within chunk
        *(uint2*)(g_xa + ((size_t)tile * NKC + kc2) * TILE_A + (ksub << 14)
                  + sw128((uint32_t)(r * 128 + (f & 15) * 8))) = hv;
    }
}

// ======================= K4: grouped GEMM (lockstep, 2-stage, BK=128) =======================
__device__ __forceinline__ void issue_stage(uint32_t A0, uint32_t mb, int chunk, int stage,
                                            int mt, int e, int nt) {
    uint32_t bar = mb + stage * 8;
    MBARRIER_EXPECT_TX(bar, (uint32_t)STAGE_SZ);
    const char* asrc = g_xa + ((size_t)(mt * NKC + chunk)) * TILE_A;
    const char* bsrc = g_wb + ((size_t)((e * NNT + nt) * NKC + chunk)) * TILE_B;
    uint32_t sb = A0 + stage * STAGE_SZ;
    bulk_g2s(sb, asrc, TILE_A, bar);
    bulk_g2s(sb + OFF_B, bsrc, TILE_B, bar);
}

__global__ void __launch_bounds__(GTHREADS, 1)
k_gemm(const float* __restrict__ bias, float* __restrict__ out)
{
    const int m0p = blockIdx.y * BM;
    if (m0p >= d_poff[NEXP]) return;
    int e = 0;
#pragma unroll
    for (int i = 0; i < NEXP; i++) if (m0p >= d_poff[i + 1]) e = i + 1;

    const int mt = blockIdx.y;
    const int nt = blockIdx.x;
    const int n0 = nt * BN;

    extern __shared__ char smraw[];
    const uint32_t A0 = (smem_u32(smraw) + 1023u) & ~1023u;
    const uint32_t mb = A0 + OFF_MB;

    const int tid = threadIdx.x;
    const int wid = tid >> 5;
    const int lane = tid & 31;
    const int warp_m = wid >> 3;     // 0..1 -> 64 m-rows
    const int warp_n = wid & 7;      // 0..7 -> 32 n-cols

    int* rows = (int*)(smraw + ((A0 + OFF_ROWS) - smem_u32(smraw)));
    if (tid < BM) rows[tid] = d_perm[m0p + tid];
    if (tid == 0) {
        MBARRIER_INIT(mb, 1);
        MBARRIER_INIT(mb + 8, 1);
    }
    __syncthreads();

    if (tid == 0) issue_stage(A0, mb, 0, 0, mt, e, nt);

    float acc[4][4][4];
#pragma unroll
    for (int i = 0; i < 4; i++)
#pragma unroll
        for (int j = 0; j < 4; j++)
#pragma unroll
            for (int q = 0; q < 4; q++) acc[i][j][q] = 0.0f;

    // ---- A fragment base offsets (non-trans ldsm, [m][k] subtiles) ----
    const int lrow = lane & 15;
    const int lc16 = (lane >> 4) << 4;
    uint32_t a0off[4];
#pragma unroll
    for (int i = 0; i < 4; i++)
        a0off[i] = sw128((uint32_t)((warp_m * 64 + i * 16 + lrow) * 128 + lc16));

    // ---- B fragment base offsets (trans ldsm, [k][n] subtiles) ----
    // lane -> block: 0-7:(ng0,klo) 8-15:(ng1,klo) 16-23:(ng0,khi) 24-31:(ng1,khi)
    const int blk = lane >> 3;
    const int ng = blk & 1;
    const int base_k = (blk >> 1) * 8 + (lane & 7);
    uint32_t b0off[2];
#pragma unroll
    for (int g = 0; g < 2; g++) {
        int nn = (warp_n & 1) * 32 + g * 16 + ng * 8;    // n within 64-subtile
        b0off[g] = ((uint32_t)(warp_n >> 1) << 14)
                 + sw128((uint32_t)(base_k * 128 + nn * 2));
    }

    for (int c = 0; c < NKC; c++) {
        const int s = c & 1;
        if (tid == 0 && c + 1 < NKC) issue_stage(A0, mb, c + 1, (c + 1) & 1, mt, e, nt);

        MBARRIER_WAIT_PARITY(mb + s * 8, (c >> 1) & 1);

        const uint32_t aA = A0 + s * STAGE_SZ;
        const uint32_t aB = aA + OFF_B;
#pragma unroll
        for (int ks = 0; ks < 8; ks++) {
            uint32_t af[4][4];
            const uint32_t asub = aA + ((uint32_t)(ks >> 2) << 14);
            const uint32_t akx = (uint32_t)((ks & 3) << 5);
#pragma unroll
            for (int i = 0; i < 4; i++) ldsm_x4(af[i], asub + (a0off[i] ^ akx));
            uint32_t bf[2][4];
            const uint32_t bofs = aB + ((uint32_t)ks << 11);
#pragma unroll
            for (int g = 0; g < 2; g++) ldsm_x4_t(bf[g], bofs + b0off[g]);
#pragma unroll
            for (int i = 0; i < 4; i++)
#pragma unroll
                for (int j = 0; j < 4; j++)
                    mma16816(acc[i][j], af[i], bf[j >> 1][j & 1], bf[j >> 1][(j & 1) + 2]);
        }
        __syncthreads();
    }

    // epilogue: add bias, scatter rows
    const float* be = bias + (size_t)e * DIM;
#pragma unroll
    for (int i = 0; i < 4; i++) {
#pragma unroll
        for (int half = 0; half < 2; half++) {
            int mloc = warp_m * 64 + i * 16 + (lane >> 2) + half * 8;
            int grow = rows[mloc];
            if (grow < 0) continue;
            float* orow = out + (size_t)grow * DIM;
#pragma unroll
            for (int j = 0; j < 4; j++) {
                int col = n0 + warp_n * 32 + j * 8 + (lane & 3) * 2;
                float2 bb = *(const float2*)(be + col);
                float2 o;
                o.x = acc[i][j][half * 2 + 0] + bb.x;
                o.y = acc[i][j][half * 2 + 1] + bb.y;
                *(float2*)(orow + col) = o;
            }
        }
    }
}

// ======================= host =======================
extern "C" void kernel_launch(void* const* d_in, const int* in_sizes, int n_in,
                              void* d_out, int out_size)
{
    const float* x = nullptr;
    const float* W = nullptr;
    const float* b = nullptr;
    const void* idx = nullptr;
    for (int i = 0; i < n_in; i++) {
        long long sz = in_sizes[i];
        if      (sz == (long long)B_TOK * DIM)      x = (const float*)d_in[i];
        else if (sz == (long long)NEXP * DIM * DIM) W = (const float*)d_in[i];
        else if (sz == (long long)NEXP * DIM)       b = (const float*)d_in[i];
        else if (sz == (long long)B_TOK)            idx = d_in[i];
    }
    float* out = (float*)d_out;
    const int* v32 = (const int*)idx;

    cudaFuncSetAttribute(k_gemm, cudaFuncAttributeMaxDynamicSharedMemorySize, SMEM_REQ);

    dim3 wgrid(NNT, NKC, NEXP);                      // 1024 blocks
    k1_convw_init<<<wgrid, 256>>>(W, v32);           // launch 1
    k2_hist_scan<<<NTB, 256>>>(v32);                 // launch 2
    k3_scatter_convx<<<dim3(NTB, 8), 256>>>(v32, x); // launch 3
    dim3 ggrid(NNT, MAXTILES);
    k_gemm<<<ggrid, GTHREADS, SMEM_REQ>>>(b, out);   // launch 4 (ncu target)
}